// round 4
// baseline (speedup 1.0000x reference)
#include <cuda_runtime.h>
#include <cuda_fp16.h>
#include <math.h>

// Problem dims
#define Bb 256
#define Tt 256
#define Mm 512
#define Pp 512
#define ATTN_OFF 262144          // B*1024 head elems, then attn [B,T,T]

// ------------------- device globals (no allocation allowed) -------------------
__device__ __half g_UHh[33554432];         // [B*T, M] fp16  (67 MB)
__device__ __half g_Hh [33554432];         // fp16 copy of H (67 MB)
__device__ float  g_WdT[1024 * 512];       // W_d^T : [k=1024][col=512]
__device__ float  g_UdT[512 * 512];        // U_d^T : [m=512][n=512]
__device__ float  g_WT [1024 * 2048];      // [W_ih^T ; W_hh^T] : [k=1024][g=2048]
__device__ float  g_d  [Bb * Pp];
__device__ float  g_s  [Bb * Pp];
__device__ float  g_ct [Bb * Mm];
__device__ float  g_wqp[4 * Bb * Mm];      // 4 k-quarter partials of wq
__device__ float  g_part[2 * Bb * 2048];   // 2 k-half partials of gates

// software grid barrier state
__device__ unsigned g_bar_count = 0;
__device__ unsigned g_bar_gen   = 0;

// ------------------- helpers -------------------
__device__ __forceinline__ float tanh_fast(float x) {
    float y;
    asm("tanh.approx.f32 %0, %1;" : "=f"(y) : "f"(x));
    return y;
}
__device__ __forceinline__ unsigned long long pack2(float x) {
    unsigned long long r;
    asm("mov.b64 %0, {%1, %1};" : "=l"(r) : "f"(x));
    return r;
}
__device__ __forceinline__ void fma2(unsigned long long& d,
                                     unsigned long long a, unsigned long long b) {
    asm("fma.rn.f32x2 %0, %1, %2, %0;" : "+l"(d) : "l"(a), "l"(b));
}
__device__ __forceinline__ float2 unpack2(unsigned long long a) {
    float2 f;
    asm("mov.b64 {%0, %1}, %2;" : "=f"(f.x), "=f"(f.y) : "l"(a));
    return f;
}

// grid-wide barrier: leader thread does global handshake, rest wait at bar.sync
__device__ __forceinline__ void gsync(int G) {
    __syncthreads();
    if (threadIdx.x == 0) {
        volatile unsigned* genp = (volatile unsigned*)&g_bar_gen;
        unsigned gen = *genp;
        __threadfence();
        if (atomicAdd(&g_bar_count, 1u) == (unsigned)(G - 1)) {
            g_bar_count = 0;
            __threadfence();
            *genp = gen + 1;
        } else {
            while (*genp == gen) { }
            __threadfence();
        }
    }
    __syncthreads();
}

// ------------------- the single persistent kernel -------------------
__global__ void __launch_bounds__(256, 2)
k_decoder(const float* __restrict__ H,  const float* __restrict__ d0,
          const float* __restrict__ s0, const float* __restrict__ W_d,
          const float* __restrict__ U_d, const float* __restrict__ v_d,
          const float* __restrict__ W_ih, const float* __restrict__ W_hh,
          const float* __restrict__ b_ih, const float* __restrict__ b_hh,
          float* __restrict__ out, int G) {
    __shared__ __align__(16) float sm[9216];   // 36.8 KB, reused per phase

    const int tid = threadIdx.x;
    const int bid = blockIdx.x;
    const int gtid = bid * 256 + tid;
    const int nthr = G * 256;

    // ---------------- phase T: transposes, init, fp16 H copy ----------------
    for (int i = gtid; i < 524288; i += nthr) {          // W_d [512,1024] -> WdT[k][col]
        int n = i >> 10, j = i & 1023;
        g_WdT[j * 512 + n] = W_d[i];
    }
    for (int i = gtid; i < 262144; i += nthr) {          // U_d [512,512] -> UdT[m][n]
        int n = i >> 9, m = i & 511;
        g_UdT[m * 512 + n] = U_d[i];
    }
    for (int i = gtid; i < 1048576; i += nthr) {         // W_ih/W_hh [2048,512] -> WT[k][g]
        int gcol = i >> 9, m = i & 511;
        g_WT[(size_t)m * 2048 + gcol] = W_ih[i];
        g_WT[(size_t)(512 + m) * 2048 + gcol] = W_hh[i];
    }
    for (int i = gtid; i < 131072; i += nthr) {          // state init
        g_d[i] = d0[i];
        g_s[i] = s0[i];
    }
    for (int i = gtid; i < 33554432; i += nthr)          // H fp16 copy for ct
        g_Hh[i] = __float2half_rn(H[i]);
    gsync(G);

    // ---------------- phase U: UH = H @ UdT, fp16 out ----------------
    // tile = 8 rows of H; thread owns 2 output cols, f32x2 over row pairs
    for (int tile = bid; tile < 8192; tile += G) {
        const int i0 = tile * 8;
        __syncthreads();
        for (int idx = tid; idx < 4096; idx += 256) {    // Hs[m*10 + r] transposed
            int r = idx >> 9, m = idx & 511;
            sm[m * 10 + r] = H[(size_t)(i0 + r) * 512 + m];
        }
        __syncthreads();

        const int c0 = 2 * tid;
        unsigned long long acc0[4] = {0, 0, 0, 0};
        unsigned long long acc1[4] = {0, 0, 0, 0};
#pragma unroll 4
        for (int m = 0; m < 512; m++) {
            float2 w = *(const float2*)&g_UdT[m * 512 + c0];
            unsigned long long w20 = pack2(w.x), w21 = pack2(w.y);
            const float* hr = &sm[m * 10];
#pragma unroll
            for (int rp = 0; rp < 4; rp++) {
                unsigned long long h2 = *(const unsigned long long*)&hr[2 * rp];
                fma2(acc0[rp], w20, h2);
                fma2(acc1[rp], w21, h2);
            }
        }
#pragma unroll
        for (int rp = 0; rp < 4; rp++) {
            float2 a0 = unpack2(acc0[rp]);   // col c0,   rows 2rp / 2rp+1
            float2 a1 = unpack2(acc1[rp]);   // col c0+1
            __half2* dst0 = (__half2*)&g_UHh[(size_t)(i0 + 2 * rp) * 512 + c0];
            __half2* dst1 = (__half2*)&g_UHh[(size_t)(i0 + 2 * rp + 1) * 512 + c0];
            *dst0 = __floats2half2_rn(a0.x, a1.x);
            *dst1 = __floats2half2_rn(a0.y, a1.y);
        }
    }
    gsync(G);

    // ---------------- main scan: 256 steps ----------------
    for (int step = 0; step < 256; ++step) {
        // ---- P1: wq partials. tile = 8 batches x 256 cols x 256 k ----
        for (int tile = bid; tile < 256; tile += G) {
            const int bg = tile >> 3, cs = (tile >> 2) & 1, kq = tile & 3;
            const int b0 = bg * 8;
            const int col = cs * 256 + tid;
            const float* qsrc = (kq < 2) ? g_d : g_s;
            const int koff = (kq & 1) * 256;
            __syncthreads();
            for (int idx = tid; idx < 2048; idx += 256) { // qs[kk*10 + r]
                int r = idx >> 8, kk = idx & 255;
                sm[kk * 10 + r] = qsrc[(b0 + r) * 512 + koff + kk];
            }
            __syncthreads();

            unsigned long long acc[4] = {0, 0, 0, 0};
            const float* wcol = &g_WdT[(kq * 256) * 512 + col];
#pragma unroll 4
            for (int kk = 0; kk < 256; kk++) {
                unsigned long long w2 = pack2(wcol[kk * 512]);
                const float* qr = &sm[kk * 10];
#pragma unroll
                for (int rp = 0; rp < 4; rp++)
                    fma2(acc[rp], w2, *(const unsigned long long*)&qr[2 * rp]);
            }
            float* dst = &g_wqp[kq * 131072];
#pragma unroll
            for (int rp = 0; rp < 4; rp++) {
                float2 a = unpack2(acc[rp]);
                dst[(b0 + 2 * rp) * 512 + col] = a.x;
                dst[(b0 + 2 * rp + 1) * 512 + col] = a.y;
            }
        }
        gsync(G);

        // ---- P2: e + softmax + attn + ct. task = one batch ----
        for (int b = bid; b < 256; b += G) {
            float* wqs  = sm;          // 512
            float* vs   = sm + 512;    // 512
            float* es   = sm + 1024;   // 256
            float* beta = sm + 1280;   // 256
            float* red  = sm + 1536;   // 8
            __syncthreads();
            for (int i = tid; i < 512; i += 256) {
                float w = ((g_wqp[b * 512 + i] + g_wqp[131072 + b * 512 + i])
                           + g_wqp[262144 + b * 512 + i]) + g_wqp[393216 + b * 512 + i];
                wqs[i] = w;
                vs[i] = v_d[i];
            }
            __syncthreads();

            // e[t] = v . tanh(wq + UH[b,t,:]) ; warp w owns t = w*32..w*32+31
            const int w = tid >> 5, lane = tid & 31;
            const __half* uhb = &g_UHh[(size_t)b * 131072];
            for (int tt = 0; tt < 32; tt++) {
                const int t = w * 32 + tt;
                const __half* uhr = uhb + t * 512;
                float acc = 0.f;
#pragma unroll
                for (int ch = 0; ch < 2; ch++) {
                    const int m0 = ch * 256 + lane * 8;
                    uint4 u = *(const uint4*)(uhr + m0);
                    float2 f0 = __half22float2(*(__half2*)&u.x);
                    float2 f1 = __half22float2(*(__half2*)&u.y);
                    float2 f2 = __half22float2(*(__half2*)&u.z);
                    float2 f3 = __half22float2(*(__half2*)&u.w);
                    float4 q0 = *(const float4*)&wqs[m0];
                    float4 q1 = *(const float4*)&wqs[m0 + 4];
                    float4 v0 = *(const float4*)&vs[m0];
                    float4 v1 = *(const float4*)&vs[m0 + 4];
                    acc += v0.x * tanh_fast(f0.x + q0.x);
                    acc += v0.y * tanh_fast(f0.y + q0.y);
                    acc += v0.z * tanh_fast(f1.x + q0.z);
                    acc += v0.w * tanh_fast(f1.y + q0.w);
                    acc += v1.x * tanh_fast(f2.x + q1.x);
                    acc += v1.y * tanh_fast(f2.y + q1.y);
                    acc += v1.z * tanh_fast(f3.x + q1.z);
                    acc += v1.w * tanh_fast(f3.y + q1.w);
                }
#pragma unroll
                for (int off = 16; off; off >>= 1)
                    acc += __shfl_xor_sync(0xffffffffu, acc, off);
                if (lane == 0) es[t] = acc;
            }
            __syncthreads();

            // softmax over es[256]
            float ev = es[tid];
            float mv = ev;
#pragma unroll
            for (int off = 16; off; off >>= 1)
                mv = fmaxf(mv, __shfl_xor_sync(0xffffffffu, mv, off));
            if (lane == 0) red[w] = mv;
            __syncthreads();
            float bm = red[0];
#pragma unroll
            for (int i = 1; i < 8; i++) bm = fmaxf(bm, red[i]);
            float ex = __expf(ev - bm);
            float sv = ex;
#pragma unroll
            for (int off = 16; off; off >>= 1)
                sv += __shfl_xor_sync(0xffffffffu, sv, off);
            __syncthreads();
            if (lane == 0) red[w] = sv;
            __syncthreads();
            float bs = 0.f;
#pragma unroll
            for (int i = 0; i < 8; i++) bs += red[i];
            float bt = ex / bs;
            beta[tid] = bt;
            out[(size_t)ATTN_OFF + (size_t)b * 65536 + (size_t)step * 256 + tid] = bt;
            __syncthreads();

            // ct[b, c0..c0+1] = sum_t beta[t] * H[b,t,:] (fp16 H)
            const __half2* hb2 = (const __half2*)&g_Hh[(size_t)b * 131072];
            float2 acc = {0.f, 0.f};
#pragma unroll 4
            for (int t = 0; t < 256; t++) {
                float bv = beta[t];
                float2 hf = __half22float2(hb2[t * 256 + tid]);
                acc.x += bv * hf.x;
                acc.y += bv * hf.y;
            }
            *(float2*)&g_ct[b * 512 + 2 * tid] = acc;
        }
        gsync(G);

        // ---- P3a: gates partials. tile = 16 batches x 256 cols x 512 k ----
        for (int tile = bid; tile < 256; tile += G) {
            const int bg = tile >> 4, cs = (tile >> 1) & 7, kh = tile & 1;
            const int b0 = bg * 16;
            const int col = cs * 256 + tid;
            const float* qsrc = kh ? g_d : g_ct;
            __syncthreads();
            for (int idx = tid; idx < 8192; idx += 256) { // qs[kk*18 + r]
                int r = idx >> 9, kk = idx & 511;
                sm[kk * 18 + r] = qsrc[(b0 + r) * 512 + kk];
            }
            __syncthreads();

            unsigned long long acc[8] = {0, 0, 0, 0, 0, 0, 0, 0};
            const float* wcol = &g_WT[(size_t)(kh * 512) * 2048 + col];
#pragma unroll 4
            for (int kk = 0; kk < 512; kk++) {
                unsigned long long w2 = pack2(wcol[(size_t)kk * 2048]);
                const float* qr = &sm[kk * 18];
#pragma unroll
                for (int rp = 0; rp < 8; rp++)
                    fma2(acc[rp], w2, *(const unsigned long long*)&qr[2 * rp]);
            }
            float* dst = &g_part[kh * 524288];
#pragma unroll
            for (int rp = 0; rp < 8; rp++) {
                float2 a = unpack2(acc[rp]);
                dst[(b0 + 2 * rp) * 2048 + col] = a.x;
                dst[(b0 + 2 * rp + 1) * 2048 + col] = a.y;
            }
        }
        gsync(G);

        // ---- P3b: LSTM update ----
        for (int idx = gtid; idx < 131072; idx += nthr) {
            const int b = idx >> 9, p = idx & 511;
            const float* p0 = &g_part[b * 2048];
            const float* p1 = &g_part[524288 + b * 2048];
            float gi = (p0[p] + p1[p]) + (b_ih[p] + b_hh[p]);
            float gf = (p0[512 + p] + p1[512 + p]) + (b_ih[512 + p] + b_hh[512 + p]);
            float gg = (p0[1024 + p] + p1[1024 + p]) + (b_ih[1024 + p] + b_hh[1024 + p]);
            float go = (p0[1536 + p] + p1[1536 + p]) + (b_ih[1536 + p] + b_hh[1536 + p]);
            float si = 1.f / (1.f + __expf(-gi));
            float sf = 1.f / (1.f + __expf(-gf));
            float so = 1.f / (1.f + __expf(-go));
            float s_new = sf * g_s[idx] + si * tanh_fast(gg);
            g_s[idx] = s_new;
            g_d[idx] = so * tanh_fast(s_new);
        }
        gsync(G);
    }

    // ---------------- epilogue: out head = [d_final ; ct_last] ----------------
    for (int i = gtid; i < 262144; i += nthr) {
        int b = i >> 10, j = i & 1023;
        out[i] = (j < 512) ? g_d[b * 512 + j] : g_ct[b * 512 + (j - 512)];
    }
}

// ------------------- launch -------------------
extern "C" void kernel_launch(void* const* d_in, const int* in_sizes, int n_in,
                              void* d_out, int out_size) {
    (void)in_sizes; (void)n_in; (void)out_size;
    const float* H    = (const float*)d_in[0];
    const float* d0   = (const float*)d_in[1];
    const float* s0   = (const float*)d_in[2];
    const float* W_d  = (const float*)d_in[3];
    const float* U_d  = (const float*)d_in[4];
    const float* v_d  = (const float*)d_in[5];
    const float* W_ih = (const float*)d_in[6];
    const float* W_hh = (const float*)d_in[7];
    const float* b_ih = (const float*)d_in[8];
    const float* b_hh = (const float*)d_in[9];
    float* out = (float*)d_out;

    int dev = 0, sms = 148;
    cudaGetDevice(&dev);
    cudaDeviceGetAttribute(&sms, cudaDevAttrMultiProcessorCount, dev);
    int occ = 2;
    cudaOccupancyMaxActiveBlocksPerMultiprocessor(&occ, k_decoder, 256, 0);
    if (occ < 1) occ = 1;
    if (occ > 2) occ = 2;                    // cap: extra idle blocks only slow the barrier
    int G = sms * occ;
    if (G < 1) G = 148;

    k_decoder<<<G, 256>>>(H, d0, s0, W_d, U_d, v_d, W_ih, W_hh, b_ih, b_hh, out, G);
}